// round 1
// baseline (speedup 1.0000x reference)
#include <cuda_runtime.h>

#define B_ 256
#define T_ 128
#define D_ 512
#define U_ 1024

// Scratch for xi = x @ W_i + b  : [B, T, U] fp32 = 134 MB (static device array; no allocs)
__device__ float g_xi[(size_t)B_ * T_ * U_];

// ---------------------------------------------------------------------------
// Kernel 1: xi = x @ W_i + b
//   A = x      [M=B*T=32768, K=512]  row-major
//   B = W_i    [512, 1024]           row-major
//   C = g_xi   [32768, 1024]
// Tiling: BM=64, BN=64, BK=16, 256 threads, 4x4 per thread.
// ---------------------------------------------------------------------------
__global__ void xi_gemm_kernel(const float* __restrict__ A,
                               const float* __restrict__ Bw,
                               const float* __restrict__ bias) {
    const int BM = 64, BN = 64, BK = 16;
    __shared__ float As[BK][BM];   // transposed A tile
    __shared__ float Bs[BK][BN];

    const int tid = threadIdx.x;        // 0..255
    const int bm  = blockIdx.y * BM;
    const int bn  = blockIdx.x * BN;
    const int tx  = tid & 15;           // 0..15 (cols)
    const int ty  = tid >> 4;           // 0..15 (rows)

    float acc[4][4];
#pragma unroll
    for (int i = 0; i < 4; i++)
#pragma unroll
        for (int j = 0; j < 4; j++) acc[i][j] = 0.f;

    for (int kt = 0; kt < D_; kt += BK) {
        // Load A tile 64x16 (256 float4, 1 per thread), store transposed.
        {
            const int row = tid >> 2;       // 0..63
            const int c4  = tid & 3;        // 0..3
            float4 v = *reinterpret_cast<const float4*>(
                &A[(size_t)(bm + row) * D_ + kt + c4 * 4]);
            As[c4 * 4 + 0][row] = v.x;
            As[c4 * 4 + 1][row] = v.y;
            As[c4 * 4 + 2][row] = v.z;
            As[c4 * 4 + 3][row] = v.w;
        }
        // Load B tile 16x64 (256 float4, 1 per thread).
        {
            const int row = tid >> 4;       // 0..15
            const int c4  = tid & 15;       // 0..15
            *reinterpret_cast<float4*>(&Bs[row][c4 * 4]) =
                *reinterpret_cast<const float4*>(
                    &Bw[(size_t)(kt + row) * U_ + bn + c4 * 4]);
        }
        __syncthreads();

#pragma unroll
        for (int k = 0; k < BK; k++) {
            float4 a = *reinterpret_cast<float4*>(&As[k][ty * 4]);
            float4 b = *reinterpret_cast<float4*>(&Bs[k][tx * 4]);
            float av[4] = {a.x, a.y, a.z, a.w};
            float bv[4] = {b.x, b.y, b.z, b.w};
#pragma unroll
            for (int i = 0; i < 4; i++)
#pragma unroll
                for (int j = 0; j < 4; j++) acc[i][j] += av[i] * bv[j];
        }
        __syncthreads();
    }

#pragma unroll
    for (int i = 0; i < 4; i++) {
        const int m = bm + ty * 4 + i;
#pragma unroll
        for (int j = 0; j < 4; j++) {
            const int n = bn + tx * 4 + j;
            g_xi[(size_t)m * U_ + n] = acc[i][j] + bias[n];
        }
    }
}

// ---------------------------------------------------------------------------
// Kernel 2: one recurrence step.
//   iz  = xi[:, t, :] + h_prev @ (W_r with zeroed diagonal)
//   out[:, t, :] = clip(iz*iz - iz, -1, 1)
// h_prev rows come either from h0 (lda=U, t=0) or from out[:, t-1, :]
// (lda = T*U). Diagonal mask fused into the B-tile load.
// Tiling: BM=32, BN=64, BK=32, 128 threads, 4x4 per thread. Grid 16x8 = 128 CTAs.
// ---------------------------------------------------------------------------
__global__ void step_kernel(const float* __restrict__ Aptr, int lda,
                            const float* __restrict__ Wr,
                            int t, float* __restrict__ out) {
    const int BM = 32, BN = 64, BK = 32;
    __shared__ float As[BK][BM];   // transposed
    __shared__ float Bs[BK][BN];

    const int tid = threadIdx.x;        // 0..127
    const int bm  = blockIdx.y * BM;
    const int bn  = blockIdx.x * BN;
    const int tx  = tid & 15;           // 0..15 (cols)
    const int ty  = tid >> 4;           // 0..7  (rows)

    const float* __restrict__ xi_t = g_xi + (size_t)t * U_;  // row stride T*U
    float* __restrict__ out_t = out + (size_t)t * U_;        // row stride T*U

    float acc[4][4];
#pragma unroll
    for (int i = 0; i < 4; i++)
#pragma unroll
        for (int j = 0; j < 4; j++) acc[i][j] = 0.f;

    for (int kt = 0; kt < U_; kt += BK) {
        // A tile 32x32 = 256 float4, 2 per thread, stored transposed.
#pragma unroll
        for (int l = 0; l < 2; l++) {
            const int f   = tid + 128 * l;  // 0..255
            const int row = f >> 3;         // 0..31
            const int c4  = f & 7;          // 0..7
            float4 v = *reinterpret_cast<const float4*>(
                &Aptr[(size_t)(bm + row) * lda + kt + c4 * 4]);
            As[c4 * 4 + 0][row] = v.x;
            As[c4 * 4 + 1][row] = v.y;
            As[c4 * 4 + 2][row] = v.z;
            As[c4 * 4 + 3][row] = v.w;
        }
        // B tile 32x64 = 512 float4, 4 per thread, diagonal zeroed on the fly.
#pragma unroll
        for (int l = 0; l < 4; l++) {
            const int f   = tid + 128 * l;  // 0..511
            const int row = f >> 4;         // 0..31
            const int c4  = f & 15;         // 0..15
            const int kg  = kt + row;
            const int ng  = bn + c4 * 4;
            float4 v = *reinterpret_cast<const float4*>(
                &Wr[(size_t)kg * U_ + ng]);
            if (kg == ng + 0) v.x = 0.f;
            if (kg == ng + 1) v.y = 0.f;
            if (kg == ng + 2) v.z = 0.f;
            if (kg == ng + 3) v.w = 0.f;
            *reinterpret_cast<float4*>(&Bs[row][c4 * 4]) = v;
        }
        __syncthreads();

#pragma unroll
        for (int k = 0; k < BK; k++) {
            float4 a = *reinterpret_cast<float4*>(&As[k][ty * 4]);
            float4 b = *reinterpret_cast<float4*>(&Bs[k][tx * 4]);
            float av[4] = {a.x, a.y, a.z, a.w};
            float bv[4] = {b.x, b.y, b.z, b.w};
#pragma unroll
            for (int i = 0; i < 4; i++)
#pragma unroll
                for (int j = 0; j < 4; j++) acc[i][j] += av[i] * bv[j];
        }
        __syncthreads();
    }

    // Epilogue: add xi, nonlinearity, clip, store.
#pragma unroll
    for (int i = 0; i < 4; i++) {
        const int m = bm + ty * 4 + i;
        const size_t rowoff = (size_t)m * (T_ * U_);
#pragma unroll
        for (int j = 0; j < 4; j++) {
            const int n = bn + tx * 4 + j;
            float iz = acc[i][j] + xi_t[rowoff + n];
            float v = iz * iz - iz;
            v = fminf(1.0f, fmaxf(-1.0f, v));
            out_t[rowoff + n] = v;
        }
    }
}

extern "C" void kernel_launch(void* const* d_in, const int* in_sizes, int n_in,
                              void* d_out, int out_size) {
    const float* x   = (const float*)d_in[0];  // [B, T, D]
    const float* h0  = (const float*)d_in[1];  // [B, U]
    const float* W_i = (const float*)d_in[2];  // [D, U]
    const float* b   = (const float*)d_in[3];  // [U]
    const float* W_r = (const float*)d_in[4];  // [U, U]
    float* out = (float*)d_out;                // [B, T, U]

    // 1) xi = x @ W_i + b   (M=32768, N=1024, K=512)
    {
        dim3 grid(U_ / 64, (B_ * T_) / 64);    // 16 x 512
        xi_gemm_kernel<<<grid, 256>>>(x, W_i, b);
    }

    // 2) 128 sequential recurrence steps.
    {
        dim3 grid(U_ / 64, B_ / 32);           // 16 x 8 = 128 CTAs
        for (int t = 0; t < T_; t++) {
            const float* A = (t == 0) ? h0 : (out + (size_t)(t - 1) * U_);
            int lda        = (t == 0) ? U_ : (T_ * U_);
            step_kernel<<<grid, 128>>>(A, lda, W_r, t, out);
        }
    }
}

// round 2
// speedup vs baseline: 1.3454x; 1.3454x over previous
#include <cuda_runtime.h>

#define B_ 256
#define T_ 128
#define D_ 512
#define U_ 1024

using u64 = unsigned long long;

// Scratch for xi = x @ W_i + b : [B, T, U] fp32 (static device array; no allocs)
__device__ float g_xi[(size_t)B_ * T_ * U_];
// Per-m-group barrier counters (monotonic; memset to 0 before each launch)
__device__ unsigned g_bar[4];

// ---- packed fp32x2 helpers (Blackwell sm_100+) --------------------------
__device__ __forceinline__ u64 pack_dup(float v) {
    u64 r;
    asm("mov.b64 %0, {%1, %1};" : "=l"(r) : "f"(v));
    return r;
}
__device__ __forceinline__ void fma2(u64& acc, u64 a, u64 b) {
    asm("fma.rn.f32x2 %0, %1, %2, %0;" : "+l"(acc) : "l"(a), "l"(b));
}
__device__ __forceinline__ float2 unpack2(u64 v) {
    float2 r;
    asm("mov.b64 {%0, %1}, %2;" : "=f"(r.x), "=f"(r.y) : "l"(v));
    return r;
}

// ---------------------------------------------------------------------------
// Kernel 1: xi = x @ W_i + b   (M=B*T=32768, K=512, N=1024)  — from R1, works.
// ---------------------------------------------------------------------------
__global__ void xi_gemm_kernel(const float* __restrict__ A,
                               const float* __restrict__ Bw,
                               const float* __restrict__ bias) {
    const int BM = 64, BN = 64, BK = 16;
    __shared__ float As[BK][BM];
    __shared__ float Bs[BK][BN];

    const int tid = threadIdx.x;
    const int bm  = blockIdx.y * BM;
    const int bn  = blockIdx.x * BN;
    const int tx  = tid & 15;
    const int ty  = tid >> 4;

    float acc[4][4];
#pragma unroll
    for (int i = 0; i < 4; i++)
#pragma unroll
        for (int j = 0; j < 4; j++) acc[i][j] = 0.f;

    for (int kt = 0; kt < D_; kt += BK) {
        {
            const int row = tid >> 2;
            const int c4  = tid & 3;
            float4 v = *reinterpret_cast<const float4*>(
                &A[(size_t)(bm + row) * D_ + kt + c4 * 4]);
            As[c4 * 4 + 0][row] = v.x;
            As[c4 * 4 + 1][row] = v.y;
            As[c4 * 4 + 2][row] = v.z;
            As[c4 * 4 + 3][row] = v.w;
        }
        {
            const int row = tid >> 4;
            const int c4  = tid & 15;
            *reinterpret_cast<float4*>(&Bs[row][c4 * 4]) =
                *reinterpret_cast<const float4*>(
                    &Bw[(size_t)(kt + row) * U_ + bn + c4 * 4]);
        }
        __syncthreads();

#pragma unroll
        for (int k = 0; k < BK; k++) {
            float4 a = *reinterpret_cast<float4*>(&As[k][ty * 4]);
            float4 b = *reinterpret_cast<float4*>(&Bs[k][tx * 4]);
            float av[4] = {a.x, a.y, a.z, a.w};
            float bv[4] = {b.x, b.y, b.z, b.w};
#pragma unroll
            for (int i = 0; i < 4; i++)
#pragma unroll
                for (int j = 0; j < 4; j++) acc[i][j] += av[i] * bv[j];
        }
        __syncthreads();
    }

#pragma unroll
    for (int i = 0; i < 4; i++) {
        const int m = bm + ty * 4 + i;
#pragma unroll
        for (int j = 0; j < 4; j++) {
            const int n = bn + tx * 4 + j;
            g_xi[(size_t)m * U_ + n] = acc[i][j] + bias[n];
        }
    }
}

// ---------------------------------------------------------------------------
// Kernel 2: persistent recurrence. 128 CTAs x 128 threads, one wave.
// CTA tile: BM=64 (batch rows), BN=32 (U cols). grid = 4 m-groups x 32 n-tiles.
// Each step: iz = xi[:,t,:] + h_prev @ Wr(masked); out = clip(iz^2 - iz).
// Inter-step sync: per-m-group monotonic atomic barrier (32 CTAs/group).
// ---------------------------------------------------------------------------
#define SBM 64
#define SBN 32
#define SBK 32
#define BMP 66   // padded As row (word stride): 2-way max conflict, 8B aligned
#define BNP 40   // padded Bs row: 16B aligned, near-conflict-free
#define NCHUNK (U_ / SBK)

__global__ void __launch_bounds__(128, 1)
rnn_persistent_kernel(const float* __restrict__ h0,
                      const float* __restrict__ Wr,
                      float* __restrict__ out) {
    __shared__ float As[2][SBK][BMP];
    __shared__ float Bs[2][SBK][BNP];

    const int tid = threadIdx.x;
    const int grp = blockIdx.x >> 5;           // 0..3  (m-group)
    const int bm  = grp * SBM;
    const int bn  = (blockIdx.x & 31) * SBN;
    const int tx  = tid & 7;                   // cols: n0 = tx*4  (8*4 = 32)
    const int ty  = tid >> 3;                  // rows: m0 = ty*4  (16*4 = 64)

    // gmem load index precompute
    const int a_row[4] = { (tid + 0)   >> 3, (tid + 128) >> 3,
                           (tid + 256) >> 3, (tid + 384) >> 3 };
    const int a_c4 = tid & 7;                  // same for all l (f & 7 == tid & 7)
    const int b_row[2] = { (tid + 0) >> 3, (tid + 128) >> 3 };

    for (int t = 0; t < T_; t++) {
        const float* Ap;
        size_t lda;
        if (t == 0) { Ap = h0 + (size_t)bm * U_;                       lda = U_; }
        else        { Ap = out + (size_t)bm * (T_ * U_) + (size_t)(t - 1) * U_;
                      lda = (size_t)T_ * U_; }

        u64 acc[2][4];
#pragma unroll
        for (int i = 0; i < 2; i++)
#pragma unroll
            for (int j = 0; j < 4; j++) acc[i][j] = 0ull;

        float4 aR[4], bR[2];

        // ---- prologue: load chunk 0 ----
#pragma unroll
        for (int l = 0; l < 4; l++)
            aR[l] = *reinterpret_cast<const float4*>(
                &Ap[(size_t)a_row[l] * lda + a_c4 * 4]);
#pragma unroll
        for (int l = 0; l < 2; l++) {
            const int kg = b_row[l];
            const int ng = bn + a_c4 * 4;
            float4 v = *reinterpret_cast<const float4*>(&Wr[(size_t)kg * U_ + ng]);
            if (kg == ng + 0) v.x = 0.f;
            if (kg == ng + 1) v.y = 0.f;
            if (kg == ng + 2) v.z = 0.f;
            if (kg == ng + 3) v.w = 0.f;
            bR[l] = v;
        }
        // store chunk 0
#pragma unroll
        for (int l = 0; l < 4; l++) {
            As[0][a_c4 * 4 + 0][a_row[l]] = aR[l].x;
            As[0][a_c4 * 4 + 1][a_row[l]] = aR[l].y;
            As[0][a_c4 * 4 + 2][a_row[l]] = aR[l].z;
            As[0][a_c4 * 4 + 3][a_row[l]] = aR[l].w;
        }
#pragma unroll
        for (int l = 0; l < 2; l++)
            *reinterpret_cast<float4*>(&Bs[0][b_row[l]][a_c4 * 4]) = bR[l];
        __syncthreads();

        for (int c = 0; c < NCHUNK; c++) {
            const int buf = c & 1;
            const int ktn = (c + 1) * SBK;

            // prefetch next chunk into registers
            if (c + 1 < NCHUNK) {
#pragma unroll
                for (int l = 0; l < 4; l++)
                    aR[l] = *reinterpret_cast<const float4*>(
                        &Ap[(size_t)a_row[l] * lda + ktn + a_c4 * 4]);
#pragma unroll
                for (int l = 0; l < 2; l++) {
                    const int kg = ktn + b_row[l];
                    const int ng = bn + a_c4 * 4;
                    float4 v = *reinterpret_cast<const float4*>(
                        &Wr[(size_t)kg * U_ + ng]);
                    if (kg == ng + 0) v.x = 0.f;
                    if (kg == ng + 1) v.y = 0.f;
                    if (kg == ng + 2) v.z = 0.f;
                    if (kg == ng + 3) v.w = 0.f;
                    bR[l] = v;
                }
            }

            // compute on current buffer
#pragma unroll
            for (int k = 0; k < SBK; k++) {
                u64 a0 = *reinterpret_cast<const u64*>(&As[buf][k][ty * 4 + 0]);
                u64 a1 = *reinterpret_cast<const u64*>(&As[buf][k][ty * 4 + 2]);
                float4 b = *reinterpret_cast<const float4*>(&Bs[buf][k][tx * 4]);
                u64 b0 = pack_dup(b.x);
                u64 b1 = pack_dup(b.y);
                u64 b2 = pack_dup(b.z);
                u64 b3 = pack_dup(b.w);
                fma2(acc[0][0], a0, b0); fma2(acc[1][0], a1, b0);
                fma2(acc[0][1], a0, b1); fma2(acc[1][1], a1, b1);
                fma2(acc[0][2], a0, b2); fma2(acc[1][2], a1, b2);
                fma2(acc[0][3], a0, b3); fma2(acc[1][3], a1, b3);
            }
            __syncthreads();

            if (c + 1 < NCHUNK) {
                const int nb = buf ^ 1;
#pragma unroll
                for (int l = 0; l < 4; l++) {
                    As[nb][a_c4 * 4 + 0][a_row[l]] = aR[l].x;
                    As[nb][a_c4 * 4 + 1][a_row[l]] = aR[l].y;
                    As[nb][a_c4 * 4 + 2][a_row[l]] = aR[l].z;
                    As[nb][a_c4 * 4 + 3][a_row[l]] = aR[l].w;
                }
#pragma unroll
                for (int l = 0; l < 2; l++)
                    *reinterpret_cast<float4*>(&Bs[nb][b_row[l]][a_c4 * 4]) = bR[l];
                __syncthreads();
            }
        }

        // ---- epilogue: iz = acc + xi; v = iz^2 - iz; clip; store ----
        float vals[4][4];
#pragma unroll
        for (int i = 0; i < 2; i++)
#pragma unroll
            for (int j = 0; j < 4; j++) {
                float2 p = unpack2(acc[i][j]);
                vals[2 * i + 0][j] = p.x;
                vals[2 * i + 1][j] = p.y;
            }
#pragma unroll
        for (int r = 0; r < 4; r++) {
            const int m = bm + ty * 4 + r;
            const size_t base = (size_t)m * (T_ * U_) + (size_t)t * U_ + bn + tx * 4;
            float4 xv = *reinterpret_cast<const float4*>(&g_xi[base]);
            float4 o;
            float iz;
            iz = vals[r][0] + xv.x; o.x = fminf(1.f, fmaxf(-1.f, iz * iz - iz));
            iz = vals[r][1] + xv.y; o.y = fminf(1.f, fmaxf(-1.f, iz * iz - iz));
            iz = vals[r][2] + xv.z; o.z = fminf(1.f, fmaxf(-1.f, iz * iz - iz));
            iz = vals[r][3] + xv.w; o.w = fminf(1.f, fmaxf(-1.f, iz * iz - iz));
            *reinterpret_cast<float4*>(&out[base]) = o;
        }

        // ---- inter-CTA barrier (per m-group, 32 CTAs) ----
        if (t + 1 < T_) {
            __syncthreads();   // CTA-scope fence; orders all threads' stores
            if (tid == 0) {
                __threadfence();                       // release
                atomicAdd(&g_bar[grp], 1u);
                const unsigned tgt = 32u * (unsigned)(t + 1);
                while (*(volatile unsigned*)&g_bar[grp] < tgt) { }
                __threadfence();                       // acquire
            }
            __syncthreads();
        }
    }
}

extern "C" void kernel_launch(void* const* d_in, const int* in_sizes, int n_in,
                              void* d_out, int out_size) {
    const float* x   = (const float*)d_in[0];  // [B, T, D]
    const float* h0  = (const float*)d_in[1];  // [B, U]
    const float* W_i = (const float*)d_in[2];  // [D, U]
    const float* b   = (const float*)d_in[3];  // [U]
    const float* W_r = (const float*)d_in[4];  // [U, U]
    float* out = (float*)d_out;                // [B, T, U]

    // reset barrier counters (graph-capturable memset node)
    void* bar_addr = nullptr;
    cudaGetSymbolAddress(&bar_addr, g_bar);
    cudaMemsetAsync(bar_addr, 0, 4 * sizeof(unsigned));

    // 1) xi = x @ W_i + b
    {
        dim3 grid(U_ / 64, (B_ * T_) / 64);
        xi_gemm_kernel<<<grid, 256>>>(x, W_i, b);
    }

    // 2) persistent recurrence: all 128 steps in one launch
    rnn_persistent_kernel<<<128, 128>>>(h0, W_r, out);
}

// round 3
// speedup vs baseline: 1.4102x; 1.0482x over previous
#include <cuda_runtime.h>

#define B_ 256
#define T_ 128
#define D_ 512
#define U_ 1024

using u64 = unsigned long long;

// Static device scratch (no allocs allowed)
__device__ float g_xi[(size_t)B_ * T_ * U_];   // xi = x @ W_i + b
__device__ float g_Wrm[(size_t)U_ * U_];       // W_r with diagonal zeroed
__device__ unsigned g_bar[8];                  // per-m-group barrier counters

// ---- packed fp32x2 helpers (sm_100+) ----
__device__ __forceinline__ u64 pack_dup(float v) {
    u64 r;
    asm("mov.b64 %0, {%1, %1};" : "=l"(r) : "f"(v));
    return r;
}
__device__ __forceinline__ void fma2(u64& acc, u64 a, u64 b) {
    asm("fma.rn.f32x2 %0, %1, %2, %0;" : "+l"(acc) : "l"(a), "l"(b));
}
__device__ __forceinline__ float2 unpack2(u64 v) {
    float2 r;
    asm("mov.b64 {%0, %1}, %2;" : "=f"(r.x), "=f"(r.y) : "l"(v));
    return r;
}

// ---------------------------------------------------------------------------
// Kernel 0: g_Wrm = W_r with zeroed diagonal. 1024x1024, float4 granularity.
// ---------------------------------------------------------------------------
__global__ void mask_wr_kernel(const float* __restrict__ Wr) {
    const int gid = blockIdx.x * 256 + threadIdx.x;      // 0..262143 (float4 id)
    const int r   = gid >> 8;                            // row (256 f4 per row)
    const int c0  = (gid & 255) * 4;                     // first col of quad
    float4 v = *reinterpret_cast<const float4*>(&Wr[(size_t)r * U_ + c0]);
    if (r == c0 + 0) v.x = 0.f;
    if (r == c0 + 1) v.y = 0.f;
    if (r == c0 + 2) v.z = 0.f;
    if (r == c0 + 3) v.w = 0.f;
    *reinterpret_cast<float4*>(&g_Wrm[(size_t)r * U_ + c0]) = v;
}

// ---------------------------------------------------------------------------
// Kernel 1: xi = x @ W_i + b   (M=32768, K=512, N=1024)
// Tile 128x64, BK=16, 256 threads, per-thread 8m x 4n via f32x2.
// ---------------------------------------------------------------------------
#define XBM 128
#define XBN 64
#define XBK 16
#define XMP 132   // padded As row

__global__ void __launch_bounds__(256)
xi_gemm_kernel(const float* __restrict__ A,
               const float* __restrict__ Bw,
               const float* __restrict__ bias) {
    __shared__ float As[2][XBK][XMP];
    __shared__ float Bs[2][XBK][XBN];

    const int tid = threadIdx.x;
    const int bm  = blockIdx.y * XBM;
    const int bn  = blockIdx.x * XBN;
    const int tx  = tid & 15;          // n block: n0 = tx*4
    const int ty  = tid >> 4;          // m block: m0 = ty*8
    const int n0  = tx * 4;
    const int m0  = ty * 8;

    // gmem load indices
    const int a_row0 = (tid + 0)   >> 2;   // 0..63
    const int a_row1 = (tid + 256) >> 2;   // 64..127
    const int a_c4   = tid & 3;            // k quad
    const int b_row  = tid >> 4;           // 0..15
    const int b_c4   = tid & 15;

    u64 acc[4][4];
#pragma unroll
    for (int i = 0; i < 4; i++)
#pragma unroll
        for (int j = 0; j < 4; j++) acc[i][j] = 0ull;

    float4 aR0, aR1, bR;
    // prologue chunk 0
    aR0 = *reinterpret_cast<const float4*>(&A[(size_t)(bm + a_row0) * D_ + a_c4 * 4]);
    aR1 = *reinterpret_cast<const float4*>(&A[(size_t)(bm + a_row1) * D_ + a_c4 * 4]);
    bR  = *reinterpret_cast<const float4*>(&Bw[(size_t)b_row * U_ + bn + b_c4 * 4]);
    {
        As[0][a_c4 * 4 + 0][a_row0] = aR0.x;
        As[0][a_c4 * 4 + 1][a_row0] = aR0.y;
        As[0][a_c4 * 4 + 2][a_row0] = aR0.z;
        As[0][a_c4 * 4 + 3][a_row0] = aR0.w;
        As[0][a_c4 * 4 + 0][a_row1] = aR1.x;
        As[0][a_c4 * 4 + 1][a_row1] = aR1.y;
        As[0][a_c4 * 4 + 2][a_row1] = aR1.z;
        As[0][a_c4 * 4 + 3][a_row1] = aR1.w;
        *reinterpret_cast<float4*>(&Bs[0][b_row][b_c4 * 4]) = bR;
    }
    __syncthreads();

    const int NCH = D_ / XBK;   // 32
    for (int c = 0; c < NCH; c++) {
        const int buf = c & 1;
        const int ktn = (c + 1) * XBK;
        if (c + 1 < NCH) {
            aR0 = *reinterpret_cast<const float4*>(&A[(size_t)(bm + a_row0) * D_ + ktn + a_c4 * 4]);
            aR1 = *reinterpret_cast<const float4*>(&A[(size_t)(bm + a_row1) * D_ + ktn + a_c4 * 4]);
            bR  = *reinterpret_cast<const float4*>(&Bw[(size_t)(ktn + b_row) * U_ + bn + b_c4 * 4]);
        }
#pragma unroll
        for (int k = 0; k < XBK; k++) {
            ulonglong2 aa0 = *reinterpret_cast<const ulonglong2*>(&As[buf][k][m0]);
            ulonglong2 aa1 = *reinterpret_cast<const ulonglong2*>(&As[buf][k][m0 + 4]);
            float4 b = *reinterpret_cast<const float4*>(&Bs[buf][k][n0]);
            u64 b0 = pack_dup(b.x), b1 = pack_dup(b.y);
            u64 b2 = pack_dup(b.z), b3 = pack_dup(b.w);
            fma2(acc[0][0], aa0.x, b0); fma2(acc[1][0], aa0.y, b0);
            fma2(acc[2][0], aa1.x, b0); fma2(acc[3][0], aa1.y, b0);
            fma2(acc[0][1], aa0.x, b1); fma2(acc[1][1], aa0.y, b1);
            fma2(acc[2][1], aa1.x, b1); fma2(acc[3][1], aa1.y, b1);
            fma2(acc[0][2], aa0.x, b2); fma2(acc[1][2], aa0.y, b2);
            fma2(acc[2][2], aa1.x, b2); fma2(acc[3][2], aa1.y, b2);
            fma2(acc[0][3], aa0.x, b3); fma2(acc[1][3], aa0.y, b3);
            fma2(acc[2][3], aa1.x, b3); fma2(acc[3][3], aa1.y, b3);
        }
        __syncthreads();
        if (c + 1 < NCH) {
            const int nb = (c + 1) & 1;
            As[nb][a_c4 * 4 + 0][a_row0] = aR0.x;
            As[nb][a_c4 * 4 + 1][a_row0] = aR0.y;
            As[nb][a_c4 * 4 + 2][a_row0] = aR0.z;
            As[nb][a_c4 * 4 + 3][a_row0] = aR0.w;
            As[nb][a_c4 * 4 + 0][a_row1] = aR1.x;
            As[nb][a_c4 * 4 + 1][a_row1] = aR1.y;
            As[nb][a_c4 * 4 + 2][a_row1] = aR1.z;
            As[nb][a_c4 * 4 + 3][a_row1] = aR1.w;
            *reinterpret_cast<float4*>(&Bs[nb][b_row][b_c4 * 4]) = bR;
            __syncthreads();
        }
    }

    // epilogue: +bias, store 8 rows x float4
    const float4 bv = *reinterpret_cast<const float4*>(&bias[bn + n0]);
#pragma unroll
    for (int p = 0; p < 4; p++) {
        float2 r0[4];
#pragma unroll
        for (int j = 0; j < 4; j++) r0[j] = unpack2(acc[p][j]);
        const int mA = bm + m0 + 2 * p;
        float4 oA = { r0[0].x + bv.x, r0[1].x + bv.y, r0[2].x + bv.z, r0[3].x + bv.w };
        float4 oB = { r0[0].y + bv.x, r0[1].y + bv.y, r0[2].y + bv.z, r0[3].y + bv.w };
        *reinterpret_cast<float4*>(&g_xi[(size_t)mA * U_ + bn + n0]) = oA;
        *reinterpret_cast<float4*>(&g_xi[(size_t)(mA + 1) * U_ + bn + n0]) = oB;
    }
}

// ---------------------------------------------------------------------------
// Kernel 2: persistent recurrence.
// 128 CTAs x 256 threads. CTA tile 32m x 64n. grid = 8 m-groups x 16 n-tiles.
// Per-thread: 8m x 1n (4 f32x2 accs). Inner loop: 8 instr / 16 FLOP.
// ---------------------------------------------------------------------------
#define SM_ 32
#define SN_ 64
#define SK_ 32
#define SMP 36
#define SNCH (U_ / SK_)

__global__ void __launch_bounds__(256, 1)
rnn_persistent_kernel(const float* __restrict__ h0,
                      float* __restrict__ out) {
    __shared__ float As[2][SK_][SMP];
    __shared__ float Bs[2][SK_][SN_];

    const int tid = threadIdx.x;
    const int grp = blockIdx.x >> 4;          // 0..7
    const int bm  = grp * SM_;
    const int bn  = (blockIdx.x & 15) * SN_;
    const int tx  = tid & 63;                 // n index (one col per thread)
    const int m0  = (tid >> 6) * 8;           // 0,8,16,24

    // gmem A-load indices: 32x32 chunk = 256 float4, 1 per thread
    const int a_row = tid >> 3;               // 0..31
    const int a_c4  = tid & 7;                // k quad
    // gmem B-load indices: 32x64 chunk = 512 float4, 2 per thread
    const int b_row0 = (tid + 0)   >> 4;      // 0..15
    const int b_row1 = (tid + 256) >> 4;      // 16..31
    const int b_c4   = tid & 15;

    const float* __restrict__ Wr = g_Wrm;

    for (int t = 0; t < T_; t++) {
        const float* Ap;
        size_t lda;
        if (t == 0) { Ap = h0 + (size_t)bm * U_;  lda = U_; }
        else        { Ap = out + (size_t)bm * ((size_t)T_ * U_) + (size_t)(t - 1) * U_;
                      lda = (size_t)T_ * U_; }

        // prefetch xi for this thread's outputs (hidden under the k-loop)
        float xr[8];
#pragma unroll
        for (int r = 0; r < 8; r++) {
            const int m = bm + m0 + r;
            xr[r] = g_xi[(size_t)m * ((size_t)T_ * U_) + (size_t)t * U_ + bn + tx];
        }

        u64 acc[4];
#pragma unroll
        for (int p = 0; p < 4; p++) acc[p] = 0ull;

        float4 aR, bR0, bR1;
        // prologue: chunk 0
        aR  = *reinterpret_cast<const float4*>(&Ap[(size_t)a_row * lda + a_c4 * 4]);
        bR0 = *reinterpret_cast<const float4*>(&Wr[(size_t)b_row0 * U_ + bn + b_c4 * 4]);
        bR1 = *reinterpret_cast<const float4*>(&Wr[(size_t)b_row1 * U_ + bn + b_c4 * 4]);
        As[0][a_c4 * 4 + 0][a_row] = aR.x;
        As[0][a_c4 * 4 + 1][a_row] = aR.y;
        As[0][a_c4 * 4 + 2][a_row] = aR.z;
        As[0][a_c4 * 4 + 3][a_row] = aR.w;
        *reinterpret_cast<float4*>(&Bs[0][b_row0][b_c4 * 4]) = bR0;
        *reinterpret_cast<float4*>(&Bs[0][b_row1][b_c4 * 4]) = bR1;
        __syncthreads();

        for (int c = 0; c < SNCH; c++) {
            const int buf = c & 1;
            const int ktn = (c + 1) * SK_;
            if (c + 1 < SNCH) {
                aR  = *reinterpret_cast<const float4*>(&Ap[(size_t)a_row * lda + ktn + a_c4 * 4]);
                bR0 = *reinterpret_cast<const float4*>(&Wr[(size_t)(ktn + b_row0) * U_ + bn + b_c4 * 4]);
                bR1 = *reinterpret_cast<const float4*>(&Wr[(size_t)(ktn + b_row1) * U_ + bn + b_c4 * 4]);
            }
#pragma unroll
            for (int k = 0; k < SK_; k++) {
                ulonglong2 aa0 = *reinterpret_cast<const ulonglong2*>(&As[buf][k][m0]);
                ulonglong2 aa1 = *reinterpret_cast<const ulonglong2*>(&As[buf][k][m0 + 4]);
                u64 bb = pack_dup(Bs[buf][k][tx]);
                fma2(acc[0], aa0.x, bb);
                fma2(acc[1], aa0.y, bb);
                fma2(acc[2], aa1.x, bb);
                fma2(acc[3], aa1.y, bb);
            }
            __syncthreads();
            if (c + 1 < SNCH) {
                const int nb = (c + 1) & 1;
                As[nb][a_c4 * 4 + 0][a_row] = aR.x;
                As[nb][a_c4 * 4 + 1][a_row] = aR.y;
                As[nb][a_c4 * 4 + 2][a_row] = aR.z;
                As[nb][a_c4 * 4 + 3][a_row] = aR.w;
                *reinterpret_cast<float4*>(&Bs[nb][b_row0][b_c4 * 4]) = bR0;
                *reinterpret_cast<float4*>(&Bs[nb][b_row1][b_c4 * 4]) = bR1;
                __syncthreads();
            }
        }

        // epilogue: iz = acc + xi; v = iz*iz - iz; clip; store
#pragma unroll
        for (int p = 0; p < 4; p++) {
            float2 pr = unpack2(acc[p]);
            const int r0 = 2 * p, r1 = 2 * p + 1;
            const size_t b0i = (size_t)(bm + m0 + r0) * ((size_t)T_ * U_) + (size_t)t * U_ + bn + tx;
            const size_t b1i = (size_t)(bm + m0 + r1) * ((size_t)T_ * U_) + (size_t)t * U_ + bn + tx;
            float iz0 = pr.x + xr[r0];
            float iz1 = pr.y + xr[r1];
            out[b0i] = fminf(1.f, fmaxf(-1.f, iz0 * iz0 - iz0));
            out[b1i] = fminf(1.f, fmaxf(-1.f, iz1 * iz1 - iz1));
        }

        // inter-CTA barrier (per m-group, 16 CTAs)
        if (t + 1 < T_) {
            __threadfence();     // release: make this thread's stores visible
            __syncthreads();     // all threads' stores now fenced
            if (tid == 0) {
                atomicAdd(&g_bar[grp], 1u);
                const unsigned tgt = 16u * (unsigned)(t + 1);
                while (*(volatile unsigned*)&g_bar[grp] < tgt) { }
                __threadfence();  // acquire
            }
            __syncthreads();
        }
    }
}

extern "C" void kernel_launch(void* const* d_in, const int* in_sizes, int n_in,
                              void* d_out, int out_size) {
    const float* x   = (const float*)d_in[0];  // [B, T, D]
    const float* h0  = (const float*)d_in[1];  // [B, U]
    const float* W_i = (const float*)d_in[2];  // [D, U]
    const float* b   = (const float*)d_in[3];  // [U]
    const float* W_r = (const float*)d_in[4];  // [U, U]
    float* out = (float*)d_out;                // [B, T, U]

    // reset barrier counters
    void* bar_addr = nullptr;
    cudaGetSymbolAddress(&bar_addr, g_bar);
    cudaMemsetAsync(bar_addr, 0, 8 * sizeof(unsigned));

    // 0) mask W_r diagonal once per launch
    mask_wr_kernel<<<1024, 256>>>(W_r);

    // 1) xi = x @ W_i + b
    {
        dim3 grid(U_ / XBN, (B_ * T_) / XBM);  // 16 x 256
        xi_gemm_kernel<<<grid, 256>>>(x, W_i, b);
    }

    // 2) persistent recurrence: all 128 steps in one launch
    rnn_persistent_kernel<<<128, 256>>>(h0, out);
}

// round 4
// speedup vs baseline: 1.5035x; 1.0662x over previous
#include <cuda_runtime.h>

#define B_ 256
#define T_ 128
#define D_ 512
#define U_ 1024

using u64 = unsigned long long;

// Static device scratch (no allocs allowed)
__device__ float g_xi[(size_t)B_ * T_ * U_];   // xi = x @ W_i + b
__device__ unsigned g_bar[8];                  // per-m-group barrier counters

// ---- packed fp32x2 helpers (sm_100+) ----
__device__ __forceinline__ u64 pack_dup(float v) {
    u64 r;
    asm("mov.b64 %0, {%1, %1};" : "=l"(r) : "f"(v));
    return r;
}
__device__ __forceinline__ void fma2(u64& acc, u64 a, u64 b) {
    asm("fma.rn.f32x2 %0, %1, %2, %0;" : "+l"(acc) : "l"(a), "l"(b));
}
__device__ __forceinline__ float2 unpack2(u64 v) {
    float2 r;
    asm("mov.b64 {%0, %1}, %2;" : "=f"(r.x), "=f"(r.y) : "l"(v));
    return r;
}

// ---------------------------------------------------------------------------
// Kernel 1: xi = x @ W_i + b   (M=32768, K=512, N=1024)
// Tile 128x64, BK=16, 256 threads, per-thread 8m x 4n via f32x2. (R3 version)
// ---------------------------------------------------------------------------
#define XBM 128
#define XBN 64
#define XBK 16
#define XMP 132

__global__ void __launch_bounds__(256)
xi_gemm_kernel(const float* __restrict__ A,
               const float* __restrict__ Bw,
               const float* __restrict__ bias) {
    __shared__ float As[2][XBK][XMP];
    __shared__ float Bs[2][XBK][XBN];

    const int tid = threadIdx.x;
    const int bm  = blockIdx.y * XBM;
    const int bn  = blockIdx.x * XBN;
    const int tx  = tid & 15;
    const int ty  = tid >> 4;
    const int n0  = tx * 4;
    const int m0  = ty * 8;

    const int a_row0 = (tid + 0)   >> 2;
    const int a_row1 = (tid + 256) >> 2;
    const int a_c4   = tid & 3;
    const int b_row  = tid >> 4;
    const int b_c4   = tid & 15;

    u64 acc[4][4];
#pragma unroll
    for (int i = 0; i < 4; i++)
#pragma unroll
        for (int j = 0; j < 4; j++) acc[i][j] = 0ull;

    float4 aR0, aR1, bR;
    aR0 = *reinterpret_cast<const float4*>(&A[(size_t)(bm + a_row0) * D_ + a_c4 * 4]);
    aR1 = *reinterpret_cast<const float4*>(&A[(size_t)(bm + a_row1) * D_ + a_c4 * 4]);
    bR  = *reinterpret_cast<const float4*>(&Bw[(size_t)b_row * U_ + bn + b_c4 * 4]);
    {
        As[0][a_c4 * 4 + 0][a_row0] = aR0.x;
        As[0][a_c4 * 4 + 1][a_row0] = aR0.y;
        As[0][a_c4 * 4 + 2][a_row0] = aR0.z;
        As[0][a_c4 * 4 + 3][a_row0] = aR0.w;
        As[0][a_c4 * 4 + 0][a_row1] = aR1.x;
        As[0][a_c4 * 4 + 1][a_row1] = aR1.y;
        As[0][a_c4 * 4 + 2][a_row1] = aR1.z;
        As[0][a_c4 * 4 + 3][a_row1] = aR1.w;
        *reinterpret_cast<float4*>(&Bs[0][b_row][b_c4 * 4]) = bR;
    }
    __syncthreads();

    const int NCH = D_ / XBK;
    for (int c = 0; c < NCH; c++) {
        const int buf = c & 1;
        const int ktn = (c + 1) * XBK;
        if (c + 1 < NCH) {
            aR0 = *reinterpret_cast<const float4*>(&A[(size_t)(bm + a_row0) * D_ + ktn + a_c4 * 4]);
            aR1 = *reinterpret_cast<const float4*>(&A[(size_t)(bm + a_row1) * D_ + ktn + a_c4 * 4]);
            bR  = *reinterpret_cast<const float4*>(&Bw[(size_t)(ktn + b_row) * U_ + bn + b_c4 * 4]);
        }
#pragma unroll
        for (int k = 0; k < XBK; k++) {
            ulonglong2 aa0 = *reinterpret_cast<const ulonglong2*>(&As[buf][k][m0]);
            ulonglong2 aa1 = *reinterpret_cast<const ulonglong2*>(&As[buf][k][m0 + 4]);
            float4 b = *reinterpret_cast<const float4*>(&Bs[buf][k][n0]);
            u64 b0 = pack_dup(b.x), b1 = pack_dup(b.y);
            u64 b2 = pack_dup(b.z), b3 = pack_dup(b.w);
            fma2(acc[0][0], aa0.x, b0); fma2(acc[1][0], aa0.y, b0);
            fma2(acc[2][0], aa1.x, b0); fma2(acc[3][0], aa1.y, b0);
            fma2(acc[0][1], aa0.x, b1); fma2(acc[1][1], aa0.y, b1);
            fma2(acc[2][1], aa1.x, b1); fma2(acc[3][1], aa1.y, b1);
            fma2(acc[0][2], aa0.x, b2); fma2(acc[1][2], aa0.y, b2);
            fma2(acc[2][2], aa1.x, b2); fma2(acc[3][2], aa1.y, b2);
            fma2(acc[0][3], aa0.x, b3); fma2(acc[1][3], aa0.y, b3);
            fma2(acc[2][3], aa1.x, b3); fma2(acc[3][3], aa1.y, b3);
        }
        __syncthreads();
        if (c + 1 < NCH) {
            const int nb = (c + 1) & 1;
            As[nb][a_c4 * 4 + 0][a_row0] = aR0.x;
            As[nb][a_c4 * 4 + 1][a_row0] = aR0.y;
            As[nb][a_c4 * 4 + 2][a_row0] = aR0.z;
            As[nb][a_c4 * 4 + 3][a_row0] = aR0.w;
            As[nb][a_c4 * 4 + 0][a_row1] = aR1.x;
            As[nb][a_c4 * 4 + 1][a_row1] = aR1.y;
            As[nb][a_c4 * 4 + 2][a_row1] = aR1.z;
            As[nb][a_c4 * 4 + 3][a_row1] = aR1.w;
            *reinterpret_cast<float4*>(&Bs[nb][b_row][b_c4 * 4]) = bR;
            __syncthreads();
        }
    }

    const float4 bv = *reinterpret_cast<const float4*>(&bias[bn + n0]);
#pragma unroll
    for (int p = 0; p < 4; p++) {
        float2 r0[4];
#pragma unroll
        for (int j = 0; j < 4; j++) r0[j] = unpack2(acc[p][j]);
        const int mA = bm + m0 + 2 * p;
        float4 oA = { r0[0].x + bv.x, r0[1].x + bv.y, r0[2].x + bv.z, r0[3].x + bv.w };
        float4 oB = { r0[0].y + bv.x, r0[1].y + bv.y, r0[2].y + bv.z, r0[3].y + bv.w };
        *reinterpret_cast<float4*>(&g_xi[(size_t)mA * U_ + bn + n0]) = oA;
        *reinterpret_cast<float4*>(&g_xi[(size_t)(mA + 1) * U_ + bn + n0]) = oB;
    }
}

// ---------------------------------------------------------------------------
// Kernel 2: persistent recurrence with Wr stripe RESIDENT in smem.
// 128 CTAs x 256 thr. Tile 64m x 32n (4 m-groups x 32 n-tiles).
// B stripe: Wr[:, bn:bn+32] masked, 1024x32 fp32 = 128 KB in dynamic smem.
// A: 64x64 chunks, TRIPLE-buffered, one __syncthreads per chunk.
// Per-thread microtile 8m x 1n (4 f32x2 accumulators).
// ---------------------------------------------------------------------------
#define PM 64
#define PN 32
#define PK 64
#define AP 68                         // As row pad (words); keeps 16B align
#define PNCH (U_ / PK)                // 16 chunks
#define SMEM_FLOATS (U_ * PN + 3 * PK * AP)   // 32768 + 13056 = 45824
#define SMEM_BYTES (SMEM_FLOATS * 4)          // 183296

extern __shared__ float p_smem[];

__global__ void __launch_bounds__(256, 1)
rnn_persistent_kernel(const float* __restrict__ h0,
                      const float* __restrict__ Wr,
                      float* __restrict__ out) {
    float* Bs = p_smem;                 // [1024][32]
    float* As = p_smem + U_ * PN;       // [3][PK][AP]

    const int tid = threadIdx.x;
    const int grp = blockIdx.x >> 5;            // 0..3
    const int bm  = grp * PM;
    const int bn  = (blockIdx.x & 31) * PN;
    const int tx  = tid & 31;                   // n col
    const int m0  = (tid >> 5) * 8;             // 0..56

    // ---- load resident B stripe (masked diagonal), once ----
    for (int i = 0; i < 32; i++) {
        const int idx = tid + 256 * i;          // 0..8191 (float4 ids)
        const int k   = idx >> 3;
        const int c0  = (idx & 7) * 4;
        float4 v = *reinterpret_cast<const float4*>(&Wr[(size_t)k * U_ + bn + c0]);
        const int d = k - bn - c0;
        if (d == 0) v.x = 0.f;
        if (d == 1) v.y = 0.f;
        if (d == 2) v.z = 0.f;
        if (d == 3) v.w = 0.f;
        *reinterpret_cast<float4*>(&Bs[k * PN + c0]) = v;
    }
    __syncthreads();

    // A-chunk fill indices: 1024 float4 per chunk, 4 per thread.
    // idx = tid + 256*l ; kq = (idx&7) + 8*(idx>>9) ; row = (idx>>3)&63
    int f_kq[4], f_row[4];
#pragma unroll
    for (int l = 0; l < 4; l++) {
        const int idx = tid + 256 * l;
        f_kq[l]  = (idx & 7) + 8 * (idx >> 9);
        f_row[l] = (idx >> 3) & 63;
    }

    for (int t = 0; t < T_; t++) {
        const float* Ap;   // points at (row bm, col 0) of h_{t-1}
        size_t lda;
        if (t == 0) { Ap = h0 + (size_t)bm * U_;  lda = U_; }
        else        { Ap = out + (size_t)bm * ((size_t)T_ * U_) + (size_t)(t - 1) * U_;
                      lda = (size_t)T_ * U_; }

        // prefetch xi for this thread's outputs
        float xr[8];
#pragma unroll
        for (int r = 0; r < 8; r++)
            xr[r] = g_xi[(size_t)(bm + m0 + r) * ((size_t)T_ * U_) + (size_t)t * U_ + bn + tx];

        u64 acc[4];
#pragma unroll
        for (int p = 0; p < 4; p++) acc[p] = 0ull;

        float4 aR[4];

        // prologue: chunk 0 -> buf0 ; chunk 1 -> regs
#pragma unroll
        for (int l = 0; l < 4; l++)
            aR[l] = *reinterpret_cast<const float4*>(
                &Ap[(size_t)f_row[l] * lda + f_kq[l] * 4]);
#pragma unroll
        for (int l = 0; l < 4; l++) {
            float* dst = &As[0 * PK * AP + (f_kq[l] * 4) * AP + f_row[l]];
            dst[0 * AP] = aR[l].x;
            dst[1 * AP] = aR[l].y;
            dst[2 * AP] = aR[l].z;
            dst[3 * AP] = aR[l].w;
        }
        if (PNCH > 1) {
#pragma unroll
            for (int l = 0; l < 4; l++)
                aR[l] = *reinterpret_cast<const float4*>(
                    &Ap[(size_t)f_row[l] * lda + PK + f_kq[l] * 4]);
        }
        __syncthreads();

        int sbuf = 1;   // buffer for chunk c+1
        for (int c = 0; c < PNCH; c++) {
            // store chunk c+1 (in regs) into buffer (c+1)%3
            if (c + 1 < PNCH) {
                float* base = &As[sbuf * PK * AP];
#pragma unroll
                for (int l = 0; l < 4; l++) {
                    float* dst = &base[(f_kq[l] * 4) * AP + f_row[l]];
                    dst[0 * AP] = aR[l].x;
                    dst[1 * AP] = aR[l].y;
                    dst[2 * AP] = aR[l].z;
                    dst[3 * AP] = aR[l].w;
                }
            }
            // prefetch chunk c+2 into regs
            if (c + 2 < PNCH) {
                const int kt = (c + 2) * PK;
#pragma unroll
                for (int l = 0; l < 4; l++)
                    aR[l] = *reinterpret_cast<const float4*>(
                        &Ap[(size_t)f_row[l] * lda + kt + f_kq[l] * 4]);
            }
            // compute chunk c from buffer c%3
            {
                const float* abuf = &As[(c % 3) * PK * AP];
                const float* bbuf = &Bs[c * PK * PN];
#pragma unroll
                for (int k = 0; k < PK; k++) {
                    ulonglong2 aa = *reinterpret_cast<const ulonglong2*>(&abuf[k * AP + m0]);
                    ulonglong2 ab = *reinterpret_cast<const ulonglong2*>(&abuf[k * AP + m0 + 4]);
                    u64 bb = pack_dup(bbuf[k * PN + tx]);
                    fma2(acc[0], aa.x, bb);
                    fma2(acc[1], aa.y, bb);
                    fma2(acc[2], ab.x, bb);
                    fma2(acc[3], ab.y, bb);
                }
            }
            __syncthreads();
            sbuf = (sbuf + 1 == 3) ? 0 : sbuf + 1;
        }

        // epilogue: iz = acc + xi ; v = iz*iz - iz ; clip ; store
#pragma unroll
        for (int p = 0; p < 4; p++) {
            float2 pr = unpack2(acc[p]);
            const int r0 = 2 * p, r1 = 2 * p + 1;
            const size_t b0i = (size_t)(bm + m0 + r0) * ((size_t)T_ * U_) + (size_t)t * U_ + bn + tx;
            const size_t b1i = (size_t)(bm + m0 + r1) * ((size_t)T_ * U_) + (size_t)t * U_ + bn + tx;
            float iz0 = pr.x + xr[r0];
            float iz1 = pr.y + xr[r1];
            out[b0i] = fminf(1.f, fmaxf(-1.f, iz0 * iz0 - iz0));
            out[b1i] = fminf(1.f, fmaxf(-1.f, iz1 * iz1 - iz1));
        }

        // inter-CTA barrier (per m-group, 32 CTAs)
        if (t + 1 < T_) {
            __threadfence();
            __syncthreads();
            if (tid == 0) {
                atomicAdd(&g_bar[grp], 1u);
                const unsigned tgt = 32u * (unsigned)(t + 1);
                while (*(volatile unsigned*)&g_bar[grp] < tgt) { }
                __threadfence();
            }
            __syncthreads();
        }
    }
}

extern "C" void kernel_launch(void* const* d_in, const int* in_sizes, int n_in,
                              void* d_out, int out_size) {
    const float* x   = (const float*)d_in[0];  // [B, T, D]
    const float* h0  = (const float*)d_in[1];  // [B, U]
    const float* W_i = (const float*)d_in[2];  // [D, U]
    const float* b   = (const float*)d_in[3];  // [U]
    const float* W_r = (const float*)d_in[4];  // [U, U]
    float* out = (float*)d_out;                // [B, T, U]

    static bool attr_done = false;
    if (!attr_done) {
        cudaFuncSetAttribute(rnn_persistent_kernel,
                             cudaFuncAttributeMaxDynamicSharedMemorySize,
                             SMEM_BYTES);
        attr_done = true;
    }

    // reset barrier counters
    void* bar_addr = nullptr;
    cudaGetSymbolAddress(&bar_addr, g_bar);
    cudaMemsetAsync(bar_addr, 0, 8 * sizeof(unsigned));

    // 1) xi = x @ W_i + b
    {
        dim3 grid(U_ / XBN, (B_ * T_) / XBM);  // 16 x 256
        xi_gemm_kernel<<<grid, 256>>>(x, W_i, b);
    }

    // 2) persistent recurrence: all 128 steps in one launch
    rnn_persistent_kernel<<<128, 256, SMEM_BYTES>>>(h0, W_r, out);
}